// round 1
// baseline (speedup 1.0000x reference)
#include <cuda_runtime.h>
#include <math.h>

#define NPTS  65536
#define NV    512
#define KNN   8
#define HID   512
#define F0V   1563          // (V+1)*3 + 3*K
#define FIV   2075          // F0 + H
#define KP    1568          // F0 padded to /16 (zero pad)
#define NC    2048          // 4 * H  (W_first + 3x W_in latent parts)
#define ROWIN 1539          // 3 + 3*V

// ---- static scratch (no allocations allowed) ----
__device__ __align__(128) float g_X [(size_t)NPTS * KP];   // x_ padded
__device__ __align__(128) float g_P [(size_t)NPTS * NC];   // x_ @ Wcat + bcat
__device__ __align__(128) float g_Wc[(size_t)KP * NC];     // packed weights
__device__ __align__(128) float g_bc[NC];
__device__ __align__(128) float g_A0[(size_t)NPTS * HID];
__device__ __align__(128) float g_A1[(size_t)NPTS * HID];

// ---------------------------------------------------------------------------
// Stage 0: per-row 8-NN + materialize padded x_ = [xyz(3), sel(24), latent(1536), 0(5)]
// ---------------------------------------------------------------------------
__global__ void build_x_kernel(const float* __restrict__ cxyz) {
    const int row = blockIdx.x;
    const float* cr = cxyz + (size_t)row * ROWIN;
    __shared__ float sd2[NV];
    __shared__ int   sIdx[KNN];
    __shared__ float rv[128];
    __shared__ int   ri[128];
    const int tid = threadIdx.x;

    const float x = cr[0], y = cr[1], z = cr[2];
    for (int j = tid; j < NV; j += 128) {
        float dx = x - cr[3 + 3 * j];
        float dy = y - cr[4 + 3 * j];
        float dz = z - cr[5 + 3 * j];
        sd2[j] = dx * dx + dy * dy + dz * dz;
    }
    __syncthreads();

    // 8 rounds of block-wide argmin (tie -> smaller index, matching stable top_k)
    for (int s = 0; s < KNN; s++) {
        float bv = INFINITY; int bi = NV;
        for (int j = tid; j < NV; j += 128) {
            float v = sd2[j];
            if (v < bv) { bv = v; bi = j; }
        }
        rv[tid] = bv; ri[tid] = bi;
        __syncthreads();
        for (int off = 64; off > 0; off >>= 1) {
            if (tid < off) {
                float ov = rv[tid + off]; int oi = ri[tid + off];
                if (ov < rv[tid] || (ov == rv[tid] && oi < ri[tid])) { rv[tid] = ov; ri[tid] = oi; }
            }
            __syncthreads();
        }
        if (tid == 0) { sIdx[s] = ri[0]; sd2[ri[0]] = INFINITY; }
        __syncthreads();
    }

    float* xr = g_X + (size_t)row * KP;
    if (tid < 3) xr[tid] = cr[tid];
    if (tid >= 3 && tid < 27) {
        int t = tid - 3;
        xr[tid] = cr[3 + 3 * sIdx[t / 3] + (t % 3)];
    }
    if (tid >= 27 && tid < 27 + (KP - F0V)) xr[F0V + (tid - 27)] = 0.f;
    for (int j = tid; j < 3 * NV; j += 128) xr[27 + j] = cr[3 + j];
}

// ---------------------------------------------------------------------------
// Pack Wcat[k][j]: col block 0 -> W_first[k], block b -> W_in[b-1][512+k]; pad rows zero
// ---------------------------------------------------------------------------
__global__ void pack_w_kernel(const float* __restrict__ Wf, const float* __restrict__ Win) {
    const size_t total = (size_t)KP * NC;
    for (size_t idx = (size_t)blockIdx.x * blockDim.x + threadIdx.x; idx < total;
         idx += (size_t)gridDim.x * blockDim.x) {
        int k = (int)(idx / NC);
        int j = (int)(idx % NC);
        int blk = j >> 9, h = j & 511;
        float v = 0.f;
        if (k < F0V) {
            if (blk == 0) v = Wf[(size_t)k * HID + h];
            else          v = Win[(size_t)(blk - 1) * FIV * HID + (size_t)(HID + k) * HID + h];
        }
        g_Wc[idx] = v;
    }
}

__global__ void pack_b_kernel(const float* __restrict__ bf, const float* __restrict__ bin) {
    int j = blockIdx.x * blockDim.x + threadIdx.x;
    if (j < NC) {
        int blk = j >> 9, h = j & 511;
        g_bc[j] = (blk == 0) ? bf[h] : bin[(blk - 1) * HID + h];
    }
}

// ---------------------------------------------------------------------------
// Generic fp32 GEMM: Y = act( maybeRelu(A) @ W + addend )
//   addend: bias vector (addIsMat=0) or per-element matrix slice (addIsMat=1)
//   BM=BN=128, BK=16, 256 threads, 8x8 register tile.
//   All dims divisible (M%128==0, N%128==0, K%16==0) -> no bounds checks.
// ---------------------------------------------------------------------------
template<bool RELU_IN>
__global__ void __launch_bounds__(256, 2)
gemm_kernel(const float* __restrict__ A, int lda,
            const float* __restrict__ W, int ldw,
            const float* __restrict__ addp, int addIsMat, int ldadd,
            float* __restrict__ Y, int ldy,
            int K, int doRelu)
{
    __shared__ __align__(16) float As[16][132];
    __shared__ __align__(16) float Bs[16][132];
    const int tid = threadIdx.x;
    const int m0 = blockIdx.y * 128;
    const int n0 = blockIdx.x * 128;
    const int rm = (tid >> 4) << 3;
    const int rn = (tid & 15) << 3;
    const float* Ab = A + (size_t)m0 * lda;
    const float* Wb = W + n0;

    float acc[8][8];
#pragma unroll
    for (int i = 0; i < 8; i++)
#pragma unroll
        for (int j = 0; j < 8; j++) acc[i][j] = 0.f;

    for (int k0 = 0; k0 < K; k0 += 16) {
#pragma unroll
        for (int t = 0; t < 2; t++) {
            int idx = tid + t * 256;
            int r = idx >> 2, c4 = (idx & 3) << 2;
            float4 v = *reinterpret_cast<const float4*>(Ab + (size_t)r * lda + k0 + c4);
            if (RELU_IN) {
                v.x = fmaxf(v.x, 0.f); v.y = fmaxf(v.y, 0.f);
                v.z = fmaxf(v.z, 0.f); v.w = fmaxf(v.w, 0.f);
            }
            As[c4 + 0][r] = v.x; As[c4 + 1][r] = v.y;
            As[c4 + 2][r] = v.z; As[c4 + 3][r] = v.w;
        }
#pragma unroll
        for (int t = 0; t < 2; t++) {
            int idx = tid + t * 256;
            int r = idx >> 5, c4 = (idx & 31) << 2;
            *reinterpret_cast<float4*>(&Bs[r][c4]) =
                *reinterpret_cast<const float4*>(Wb + (size_t)(k0 + r) * ldw + c4);
        }
        __syncthreads();
#pragma unroll
        for (int kk = 0; kk < 16; kk++) {
            float a[8], b[8];
            *reinterpret_cast<float4*>(a)     = *reinterpret_cast<float4*>(&As[kk][rm]);
            *reinterpret_cast<float4*>(a + 4) = *reinterpret_cast<float4*>(&As[kk][rm + 4]);
            *reinterpret_cast<float4*>(b)     = *reinterpret_cast<float4*>(&Bs[kk][rn]);
            *reinterpret_cast<float4*>(b + 4) = *reinterpret_cast<float4*>(&Bs[kk][rn + 4]);
#pragma unroll
            for (int i = 0; i < 8; i++)
#pragma unroll
                for (int j = 0; j < 8; j++)
                    acc[i][j] = fmaf(a[i], b[j], acc[i][j]);
        }
        __syncthreads();
    }

#pragma unroll
    for (int i = 0; i < 8; i++) {
        int row = m0 + rm + i;
#pragma unroll
        for (int j4 = 0; j4 < 8; j4 += 4) {
            float4 add;
            if (addIsMat)
                add = *reinterpret_cast<const float4*>(addp + (size_t)row * ldadd + n0 + rn + j4);
            else
                add = *reinterpret_cast<const float4*>(addp + n0 + rn + j4);
            float4 v;
            v.x = acc[i][j4 + 0] + add.x; v.y = acc[i][j4 + 1] + add.y;
            v.z = acc[i][j4 + 2] + add.z; v.w = acc[i][j4 + 3] + add.w;
            if (doRelu) {
                v.x = fmaxf(v.x, 0.f); v.y = fmaxf(v.y, 0.f);
                v.z = fmaxf(v.z, 0.f); v.w = fmaxf(v.w, 0.f);
            }
            *reinterpret_cast<float4*>(Y + (size_t)row * ldy + n0 + rn + j4) = v;
        }
    }
}

// ---------------------------------------------------------------------------
// Output: out[row] = tanh(dot(x, W_out) + b_out); one warp per row
// ---------------------------------------------------------------------------
__global__ void out_kernel(const float* __restrict__ Xin, const float* __restrict__ Wo,
                           const float* __restrict__ bo, float* __restrict__ out) {
    const int row  = blockIdx.x * 8 + (threadIdx.x >> 5);
    const int lane = threadIdx.x & 31;
    const float* xr = Xin + (size_t)row * HID;
    float s = 0.f;
    for (int j = lane; j < HID; j += 32) s += xr[j] * Wo[j];
#pragma unroll
    for (int o = 16; o > 0; o >>= 1) s += __shfl_xor_sync(0xffffffffu, s, o);
    if (lane == 0) out[row] = tanhf(s + bo[0]);
}

// ---------------------------------------------------------------------------
extern "C" void kernel_launch(void* const* d_in, const int* in_sizes, int n_in,
                              void* d_out, int out_size) {
    const float* cxyz = (const float*)d_in[0];
    const float* Wf   = (const float*)d_in[1];
    const float* bf   = (const float*)d_in[2];
    const float* Win  = (const float*)d_in[3];
    const float* bin  = (const float*)d_in[4];
    const float* Wh   = (const float*)d_in[5];
    const float* bh   = (const float*)d_in[6];
    const float* Wo   = (const float*)d_in[7];
    const float* bo   = (const float*)d_in[8];
    float* out = (float*)d_out;

    float *X, *P, *Wc, *bc, *A0, *A1;
    cudaGetSymbolAddress((void**)&X,  g_X);
    cudaGetSymbolAddress((void**)&P,  g_P);
    cudaGetSymbolAddress((void**)&Wc, g_Wc);
    cudaGetSymbolAddress((void**)&bc, g_bc);
    cudaGetSymbolAddress((void**)&A0, g_A0);
    cudaGetSymbolAddress((void**)&A1, g_A1);

    build_x_kernel<<<NPTS, 128>>>(cxyz);
    pack_w_kernel<<<2048, 256>>>(Wf, Win);
    pack_b_kernel<<<8, 256>>>(bf, bin);

    // P = x_ @ Wcat + bcat   (M=65536, K=1568, N=2048)
    dim3 gBig(NC / 128, NPTS / 128);
    gemm_kernel<false><<<gBig, 256>>>(X, KP, Wc, NC, bc, 0, 0, P, NC, KP, 0);

    dim3 gL(HID / 128, NPTS / 128);
    // block 0: x1 = relu(relu(P[:, :512]) @ Wh00 + bh00); x2 = relu(x1 @ Wh01 + bh01)
    gemm_kernel<true ><<<gL, 256>>>(P,  NC,  Wh + (size_t)0 * HID * HID, HID, bh + 0 * HID, 0, 0, A0, HID, HID, 1);
    gemm_kernel<false><<<gL, 256>>>(A0, HID, Wh + (size_t)1 * HID * HID, HID, bh + 1 * HID, 0, 0, A1, HID, HID, 1);
    // block 1
    gemm_kernel<false><<<gL, 256>>>(A1, HID, Win + (size_t)0 * FIV * HID, HID, P + 512,  1, NC, A0, HID, HID, 1);
    gemm_kernel<false><<<gL, 256>>>(A0, HID, Wh + (size_t)2 * HID * HID, HID, bh + 2 * HID, 0, 0, A1, HID, HID, 1);
    gemm_kernel<false><<<gL, 256>>>(A1, HID, Wh + (size_t)3 * HID * HID, HID, bh + 3 * HID, 0, 0, A0, HID, HID, 1);
    // block 2
    gemm_kernel<false><<<gL, 256>>>(A0, HID, Win + (size_t)1 * FIV * HID, HID, P + 1024, 1, NC, A1, HID, HID, 1);
    gemm_kernel<false><<<gL, 256>>>(A1, HID, Wh + (size_t)4 * HID * HID, HID, bh + 4 * HID, 0, 0, A0, HID, HID, 1);
    gemm_kernel<false><<<gL, 256>>>(A0, HID, Wh + (size_t)5 * HID * HID, HID, bh + 5 * HID, 0, 0, A1, HID, HID, 1);
    // block 3
    gemm_kernel<false><<<gL, 256>>>(A1, HID, Win + (size_t)2 * FIV * HID, HID, P + 1536, 1, NC, A0, HID, HID, 1);
    gemm_kernel<false><<<gL, 256>>>(A0, HID, Wh + (size_t)6 * HID * HID, HID, bh + 6 * HID, 0, 0, A1, HID, HID, 1);
    gemm_kernel<false><<<gL, 256>>>(A1, HID, Wh + (size_t)7 * HID * HID, HID, bh + 7 * HID, 0, 0, A0, HID, HID, 1);

    out_kernel<<<NPTS / 8, 256>>>(A0, Wo, bo, out);
}

// round 5
// speedup vs baseline: 4.9525x; 4.9525x over previous
#include <cuda_runtime.h>
#include <cuda_fp16.h>
#include <math.h>
#include <stdint.h>

#define NPTS  65536
#define NV    512
#define KNN   8
#define HID   512
#define F0V   1563          // (V+1)*3 + 3*K
#define FIV   2075          // F0 + H
#define KP    1568          // F0 padded to /32
#define NC    2048          // 4*H packed first-layer columns
#define ROWIN 1539          // 3 + 3*V
#define NLAY  11            // chained 512x512 GEMMs
#define SA    40            // smem row stride in halfs (32 + 8 pad)

// ---- static scratch ----
__device__ __align__(128) __half g_X  [(size_t)NPTS * KP];      // x_ padded fp16
__device__ __align__(128) float  g_P  [(size_t)NPTS * NC];      // x_ @ Wcat + bcat (f32)
__device__ __align__(128) __half g_R  [(size_t)NPTS * HID];     // relu(P[:, :512]) fp16
__device__ __align__(128) __half g_WcT[(size_t)NC * KP];        // Wcat^T [N][K] fp16
__device__ __align__(128) __half g_BT [(size_t)NLAY * HID * HID]; // chain weights^T fp16
__device__ __align__(128) float  g_bc [NC];
__device__ __align__(128) __half g_A0 [(size_t)NPTS * HID];
__device__ __align__(128) __half g_A1 [(size_t)NPTS * HID];

// ---------------- helpers ----------------
__device__ __forceinline__ uint32_t smem_u32(const void* p) {
    uint32_t a;
    asm("{ .reg .u64 t; cvta.to.shared.u64 t, %1; cvt.u32.u64 %0, t; }" : "=r"(a) : "l"(p));
    return a;
}
#define CP_ASYNC16(dst, src) \
    asm volatile("cp.async.cg.shared.global [%0], [%1], 16;" :: "r"(dst), "l"(src))

__device__ __forceinline__ void mma16816(float* c, const uint32_t* a, const uint32_t* b) {
    asm volatile(
        "mma.sync.aligned.m16n8k16.row.col.f32.f16.f16.f32 "
        "{%0,%1,%2,%3}, {%4,%5,%6,%7}, {%8,%9}, {%0,%1,%2,%3};"
        : "+f"(c[0]), "+f"(c[1]), "+f"(c[2]), "+f"(c[3])
        : "r"(a[0]), "r"(a[1]), "r"(a[2]), "r"(a[3]), "r"(b[0]), "r"(b[1]));
}

// ---------------------------------------------------------------------------
// Stage 0: per-row 8-NN, build padded fp16 x_
// ---------------------------------------------------------------------------
__global__ void build_x_kernel(const float* __restrict__ cxyz) {
    const int row = blockIdx.x;
    const float* cr = cxyz + (size_t)row * ROWIN;
    __shared__ float sd2[NV];
    __shared__ int   sIdx[KNN];
    __shared__ float rv[128];
    __shared__ int   ri[128];
    const int tid = threadIdx.x;

    const float x = cr[0], y = cr[1], z = cr[2];
    for (int j = tid; j < NV; j += 128) {
        float dx = x - cr[3 + 3 * j], dy = y - cr[4 + 3 * j], dz = z - cr[5 + 3 * j];
        sd2[j] = dx * dx + dy * dy + dz * dz;
    }
    __syncthreads();
    for (int s = 0; s < KNN; s++) {
        float bv = INFINITY; int bi = NV;
        for (int j = tid; j < NV; j += 128) {
            float v = sd2[j];
            if (v < bv) { bv = v; bi = j; }
        }
        rv[tid] = bv; ri[tid] = bi;
        __syncthreads();
        for (int off = 64; off > 0; off >>= 1) {
            if (tid < off) {
                float ov = rv[tid + off]; int oi = ri[tid + off];
                if (ov < rv[tid] || (ov == rv[tid] && oi < ri[tid])) { rv[tid] = ov; ri[tid] = oi; }
            }
            __syncthreads();
        }
        if (tid == 0) { sIdx[s] = ri[0]; sd2[ri[0]] = INFINITY; }
        __syncthreads();
    }
    __half* xr = g_X + (size_t)row * KP;
    if (tid < 3) xr[tid] = __float2half_rn(cr[tid]);
    if (tid >= 3 && tid < 27) {
        int t = tid - 3;
        xr[tid] = __float2half_rn(cr[3 + 3 * sIdx[t / 3] + (t % 3)]);
    }
    if (tid >= 27 && tid < 27 + (KP - F0V)) xr[F0V + (tid - 27)] = __float2half_rn(0.f);
    for (int j = tid; j < 3 * NV; j += 128) xr[27 + j] = __float2half_rn(cr[3 + j]);
}

// ---------------------------------------------------------------------------
// Weight packing (transposed [N][K], fp16)
// ---------------------------------------------------------------------------
__global__ void pack_wcT_kernel(const float* __restrict__ Wf, const float* __restrict__ Win) {
    const size_t total = (size_t)NC * KP;
    for (size_t idx = (size_t)blockIdx.x * blockDim.x + threadIdx.x; idx < total;
         idx += (size_t)gridDim.x * blockDim.x) {
        int n = (int)(idx / KP), k = (int)(idx % KP);
        int blk = n >> 9, h = n & 511;
        float v = 0.f;
        if (k < F0V) {
            if (blk == 0) v = Wf[(size_t)k * HID + h];
            else          v = Win[(size_t)(blk - 1) * FIV * HID + (size_t)(HID + k) * HID + h];
        }
        g_WcT[idx] = __float2half_rn(v);
    }
}
__global__ void pack_bt_kernel(const float* __restrict__ Wh, const float* __restrict__ Win) {
    const size_t total = (size_t)NLAY * HID * HID;
    for (size_t idx = (size_t)blockIdx.x * blockDim.x + threadIdx.x; idx < total;
         idx += (size_t)gridDim.x * blockDim.x) {
        int i   = (int)(idx / (HID * HID));
        int rem = (int)(idx % (HID * HID));
        int n = rem / HID, k = rem % HID;
        float v;
        if (i % 3 == 2) { // block-entry layer: W_in x-part rows (0..H-1)
            int b = i / 3 + 1;
            v = Win[((size_t)(b - 1) * FIV + k) * HID + n];
        } else {
            int b = i / 3, l = i % 3;
            v = Wh[(((size_t)b * 2 + l) * HID + k) * HID + n];
        }
        g_BT[idx] = __float2half_rn(v);
    }
}
__global__ void pack_b_kernel(const float* __restrict__ bf, const float* __restrict__ bin) {
    int j = blockIdx.x * blockDim.x + threadIdx.x;
    if (j < NC) {
        int blk = j >> 9, h = j & 511;
        g_bc[j] = (blk == 0) ? bf[h] : bin[(blk - 1) * HID + h];
    }
}

// ---------------------------------------------------------------------------
// fp16 mma.sync GEMM: Y = act(A @ Bt^T + addend)
//   A [M][lda] fp16 row-major; Bt [Ntot][ldb] fp16 (K-major rows -> col-major B)
//   CTA 128x128, BK=32, 8 warps (2m x 4n), warp tile 64x32, double-buffered cp.async
// ---------------------------------------------------------------------------
__global__ void __launch_bounds__(256, 2)
hgemm(const __half* __restrict__ A, int lda,
      const __half* __restrict__ Bt, int ldb,
      const float* __restrict__ addp, int addIsMat, int ldadd,
      void* __restrict__ Yv, int ldy, int outF32,
      __half* __restrict__ Y2,
      int nk, int doRelu)
{
    __shared__ __align__(16) __half sh[2][2][128 * SA];
    const int tid = threadIdx.x;
    const int m0 = blockIdx.y * 128, n0 = blockIdx.x * 128;
    const int w = tid >> 5, lane = tid & 31;
    const int wm = (w >> 2) * 64, wn = (w & 3) * 32;

    const __half* Ab0 = A  + (size_t)m0 * lda;
    const __half* Bb0 = Bt + (size_t)n0 * ldb;

    float acc[4][4][4];
#pragma unroll
    for (int i = 0; i < 4; i++)
#pragma unroll
        for (int j = 0; j < 4; j++)
#pragma unroll
            for (int t = 0; t < 4; t++) acc[i][j][t] = 0.f;

    auto load_tile = [&](int s) {
        if (s < nk) {
            int st = s & 1;
            const __half* Ag = Ab0 + s * 32;
            const __half* Bg = Bb0 + s * 32;
#pragma unroll
            for (int i = 0; i < 4; i++) {
                int ch = tid + i * 256;            // 0..1023
                int ab = ch >> 9;                  // 0:A 1:B
                int idx = ch & 511;
                int r = idx >> 2, c = idx & 3;
                const __half* src = (ab ? Bg + (size_t)r * ldb : Ag + (size_t)r * lda) + c * 8;
                uint32_t dst = smem_u32(&sh[st][ab][r * SA + c * 8]);
                CP_ASYNC16(dst, src);
            }
        }
    };

    load_tile(0);
    asm volatile("cp.async.commit_group;" ::: "memory");

    for (int s = 0; s < nk; ++s) {
        load_tile(s + 1);
        asm volatile("cp.async.commit_group;" ::: "memory");
        asm volatile("cp.async.wait_group 1;" ::: "memory");
        __syncthreads();

        const __half* As = sh[s & 1][0];
        const __half* Bs = sh[s & 1][1];
#pragma unroll
        for (int kk = 0; kk < 32; kk += 16) {
            uint32_t aF[4][4], bF[4][2];
            const int ka = kk + (lane & 3) * 2;
#pragma unroll
            for (int mt = 0; mt < 4; mt++) {
                int ra = wm + mt * 16 + (lane >> 2);
                aF[mt][0] = *(const uint32_t*)&As[ra * SA + ka];
                aF[mt][1] = *(const uint32_t*)&As[(ra + 8) * SA + ka];
                aF[mt][2] = *(const uint32_t*)&As[ra * SA + ka + 8];
                aF[mt][3] = *(const uint32_t*)&As[(ra + 8) * SA + ka + 8];
            }
#pragma unroll
            for (int nt = 0; nt < 4; nt++) {
                int rb = wn + nt * 8 + (lane >> 2);
                bF[nt][0] = *(const uint32_t*)&Bs[rb * SA + ka];
                bF[nt][1] = *(const uint32_t*)&Bs[rb * SA + ka + 8];
            }
#pragma unroll
            for (int mt = 0; mt < 4; mt++)
#pragma unroll
                for (int nt = 0; nt < 4; nt++)
                    mma16816(acc[mt][nt], aF[mt], bF[nt]);
        }
        __syncthreads();
    }

    // ---- epilogue ----
    float*  Yf = (float*)Yv;
    __half* Yh = (__half*)Yv;
#pragma unroll
    for (int mt = 0; mt < 4; mt++) {
#pragma unroll
        for (int nt = 0; nt < 4; nt++) {
            const float* c = acc[mt][nt];
            int r0 = m0 + wm + mt * 16 + (lane >> 2);
            int cc = n0 + wn + nt * 8 + (lane & 3) * 2;
#pragma unroll
            for (int h = 0; h < 2; h++) {
                int r = r0 + h * 8;
                float v0 = c[2 * h + 0], v1 = c[2 * h + 1];
                if (addIsMat) {
                    float2 a2 = *(const float2*)(addp + (size_t)r * ldadd + cc);
                    v0 += a2.x; v1 += a2.y;
                } else {
                    v0 += addp[cc]; v1 += addp[cc + 1];
                }
                if (doRelu) { v0 = fmaxf(v0, 0.f); v1 = fmaxf(v1, 0.f); }
                if (outF32) {
                    *(float2*)(Yf + (size_t)r * ldy + cc) = make_float2(v0, v1);
                    if (Y2 != nullptr && cc < HID) {
                        __half2 hv = __floats2half2_rn(fmaxf(v0, 0.f), fmaxf(v1, 0.f));
                        *(__half2*)(Y2 + (size_t)r * HID + cc) = hv;
                    }
                } else {
                    *(__half2*)(Yh + (size_t)r * ldy + cc) = __floats2half2_rn(v0, v1);
                }
            }
        }
    }
}

// ---------------------------------------------------------------------------
// Output: out[row] = tanh(dot(x, W_out) + b_out)
// ---------------------------------------------------------------------------
__global__ void out_kernel(const __half* __restrict__ Xin, const float* __restrict__ Wo,
                           const float* __restrict__ bo, float* __restrict__ out) {
    const int row  = blockIdx.x * 8 + (threadIdx.x >> 5);
    const int lane = threadIdx.x & 31;
    const __half* xr = Xin + (size_t)row * HID;
    float s = 0.f;
    for (int j = lane; j < HID; j += 32) s += __half2float(xr[j]) * Wo[j];
#pragma unroll
    for (int o = 16; o > 0; o >>= 1) s += __shfl_xor_sync(0xffffffffu, s, o);
    if (lane == 0) out[row] = tanhf(s + bo[0]);
}

// ---------------------------------------------------------------------------
extern "C" void kernel_launch(void* const* d_in, const int* in_sizes, int n_in,
                              void* d_out, int out_size) {
    const float* cxyz = (const float*)d_in[0];
    const float* Wf   = (const float*)d_in[1];
    const float* bf   = (const float*)d_in[2];
    const float* Win  = (const float*)d_in[3];
    const float* bin  = (const float*)d_in[4];
    const float* Wh   = (const float*)d_in[5];
    const float* bh   = (const float*)d_in[6];
    const float* Wo   = (const float*)d_in[7];
    const float* bo   = (const float*)d_in[8];
    float* out = (float*)d_out;

    __half *X, *R, *WcT, *BT, *A0, *A1;
    float *P, *bc;
    cudaGetSymbolAddress((void**)&X,   g_X);
    cudaGetSymbolAddress((void**)&P,   g_P);
    cudaGetSymbolAddress((void**)&R,   g_R);
    cudaGetSymbolAddress((void**)&WcT, g_WcT);
    cudaGetSymbolAddress((void**)&BT,  g_BT);
    cudaGetSymbolAddress((void**)&bc,  g_bc);
    cudaGetSymbolAddress((void**)&A0,  g_A0);
    cudaGetSymbolAddress((void**)&A1,  g_A1);

    build_x_kernel<<<NPTS, 128>>>(cxyz);
    pack_wcT_kernel<<<4096, 256>>>(Wf, Win);
    pack_bt_kernel<<<2048, 256>>>(Wh, Win);
    pack_b_kernel<<<8, 256>>>(bf, bin);

    // Big GEMM: P = x_ @ Wcat + bcat (f32 out); also R = relu(P[:, :512]) fp16
    dim3 gBig(NC / 128, NPTS / 128);
    hgemm<<<gBig, 256>>>(X, KP, WcT, KP, bc, 0, 0, P, NC, 1, R, KP / 32, 0);

    // Chain of 11 GEMMs (fp16 activations)
    dim3 gL(HID / 128, NPTS / 128);
    const __half* a_in = R;
    __half* outs[2] = { A0, A1 };
    int pp = 0;
    for (int i = 0; i < NLAY; i++) {
        const __half* Bl = BT + (size_t)i * HID * HID;
        const float* addp;
        int addIsMat, ldadd;
        if (i % 3 == 2) {                       // block-entry: add P slice (includes bias)
            int b = i / 3 + 1;
            addp = P + (size_t)b * HID; addIsMat = 1; ldadd = NC;
        } else {                                // hidden: bias vector
            int b = i / 3, l = i % 3;
            addp = bh + (size_t)(b * 2 + l) * HID; addIsMat = 0; ldadd = 0;
        }
        __half* y = outs[pp];
        hgemm<<<gL, 256>>>(a_in, HID, Bl, HID, addp, addIsMat, ldadd,
                           y, HID, 0, nullptr, HID / 32, 1);
        a_in = y;
        pp ^= 1;
    }

    out_kernel<<<NPTS / 8, 256>>>(a_in, Wo, bo, out);
}